// round 7
// baseline (speedup 1.0000x reference)
#include <cuda_runtime.h>
#include <math.h>
#include <stdint.h>

// ---------------------------------------------------------------------------
// Problem constants
// ---------------------------------------------------------------------------
constexpr int H    = 2048;
constexpr int NH   = 16;
constexpr int NOPE = 128;
constexpr int ROPE = 64;
constexpr int VD   = 128;
constexpr int QR   = 1024;
constexpr int KVR  = 512;
constexpr int BB   = 2;       // batch
constexpr int S    = 2048;    // seq len
constexpr int T    = BB * S;  // 4096 tokens
constexpr float EPS = 1e-6f;
constexpr float SM_SCALE = 0.07216878364870323f; // 1/sqrt(192)

// ---------------------------------------------------------------------------
// Device scratch (allocation-free rule: __device__ globals)
// ---------------------------------------------------------------------------
__device__ float g_cq   [T * QR];
__device__ float g_qnope[T * NH * NOPE];
__device__ float g_qrope[T * NH * ROPE];
__device__ float g_ckv  [T * KVR];
__device__ float g_knope[T * NH * NOPE];
__device__ float g_v    [T * NH * VD];
__device__ float g_krope[T * ROPE];
__device__ float g_attn [T * NH * VD];
__device__ float g_ctab [S * (ROPE / 2)];
__device__ float g_stab [S * (ROPE / 2)];

// ---------------------------------------------------------------------------
// tf32 helpers
// ---------------------------------------------------------------------------
__device__ __forceinline__ float to_tf32(float x) {
    uint32_t u;
    asm("cvt.rna.tf32.f32 %0, %1;" : "=r"(u) : "f"(x));
    return __uint_as_float(u);
}
__device__ __forceinline__ float4 to_tf32x4(float4 v) {
    return make_float4(to_tf32(v.x), to_tf32(v.y), to_tf32(v.z), to_tf32(v.w));
}

__device__ __forceinline__ void mma_tf32(float& c0, float& c1, float& c2, float& c3,
                                         float a0, float a1, float a2, float a3,
                                         float b0, float b1)
{
    uint32_t ua0 = __float_as_uint(a0), ua1 = __float_as_uint(a1);
    uint32_t ua2 = __float_as_uint(a2), ua3 = __float_as_uint(a3);
    uint32_t ub0 = __float_as_uint(b0), ub1 = __float_as_uint(b1);
    asm volatile(
        "mma.sync.aligned.m16n8k8.row.col.f32.tf32.tf32.f32 "
        "{%0,%1,%2,%3}, {%4,%5,%6,%7}, {%8,%9}, {%0,%1,%2,%3};\n"
        : "+f"(c0), "+f"(c1), "+f"(c2), "+f"(c3)
        : "r"(ua0), "r"(ua1), "r"(ua2), "r"(ua3), "r"(ub0), "r"(ub1));
}

// Fragment-order smem stores used by the ATTENTION QK^T stage only.
template<int KSTEPS>
__device__ __forceinline__ void st_afrag(float* F, int m, int k, float4 v) {
    float* dst = F + (((m >> 4) * KSTEPS + (k >> 3)) * 32 + (m & 7) * 4 + (k & 3)) * 4
                   + ((m >> 3) & 1) + (((k >> 2) & 1) << 1);
    dst[0]  = to_tf32(v.x);
    dst[4]  = to_tf32(v.y);
    dst[8]  = to_tf32(v.z);
    dst[12] = to_tf32(v.w);
}
template<int KSTEPS>
__device__ __forceinline__ void st_bfrag_kvar(float* F, int r, int d, float4 v) {
    float* dst = F + (((r >> 3) * KSTEPS + (d >> 3)) * 32 + (r & 7) * 4 + (d & 3)) * 2
                   + ((d >> 2) & 1);
    dst[0] = to_tf32(v.x);
    dst[2] = to_tf32(v.y);
    dst[4] = to_tf32(v.z);
    dst[6] = to_tf32(v.w);
}

// ---------------------------------------------------------------------------
// tf32 tensor-core GEMM (proven): C[M,N] = A[M,K] @ B[K,N].
// 128x128 tile, BK=16, 256 threads, warp tile 64x32, double-buffered smem.
// ---------------------------------------------------------------------------
constexpr int AS_STRIDE = 20;
constexpr int BS_STRIDE = 136;

__global__ void __launch_bounds__(256)
tf32_gemm_kernel(const float* __restrict__ A, const float* __restrict__ B,
                 float* __restrict__ C, int M, int N, int K)
{
    __shared__ float As[2][128][AS_STRIDE];
    __shared__ float Bs[2][16][BS_STRIDE];

    const int tid  = threadIdx.x;
    const int lane = tid & 31;
    const int warp = tid >> 5;
    const int qid  = lane >> 2;
    const int rid  = lane & 3;
    const int wr   = (warp >> 2) * 64;
    const int wc   = (warp & 3) * 32;

    const int rowBase = blockIdx.y * 128;
    const int colBase = blockIdx.x * 128;

    const int ar0 = tid >> 2;
    const int ar1 = ar0 + 64;
    const int ac  = (tid & 3) * 4;
    const int bk0 = tid >> 5;
    const int bk1 = bk0 + 8;
    const int bn  = (tid & 31) * 4;
    const int gn  = colBase + bn;
    const bool bok = (gn < N);

    float acc[4][4][4];
#pragma unroll
    for (int i = 0; i < 4; i++)
#pragma unroll
        for (int j = 0; j < 4; j++)
#pragma unroll
            for (int c = 0; c < 4; c++) acc[i][j][c] = 0.f;

    const int nt = K / 16;
    float4 ra0, ra1, rb0, rb1;

    ra0 = *(const float4*)&A[(size_t)(rowBase + ar0) * K + ac];
    ra1 = *(const float4*)&A[(size_t)(rowBase + ar1) * K + ac];
    rb0 = bok ? *(const float4*)&B[(size_t)bk0 * N + gn] : make_float4(0,0,0,0);
    rb1 = bok ? *(const float4*)&B[(size_t)bk1 * N + gn] : make_float4(0,0,0,0);
    *(float4*)&As[0][ar0][ac] = to_tf32x4(ra0);
    *(float4*)&As[0][ar1][ac] = to_tf32x4(ra1);
    *(float4*)&Bs[0][bk0][bn] = to_tf32x4(rb0);
    *(float4*)&Bs[0][bk1][bn] = to_tf32x4(rb1);
    __syncthreads();

    for (int t = 0; t < nt; t++) {
        const int buf = t & 1;

        if (t + 1 < nt) {
            const int k0 = (t + 1) * 16;
            ra0 = *(const float4*)&A[(size_t)(rowBase + ar0) * K + k0 + ac];
            ra1 = *(const float4*)&A[(size_t)(rowBase + ar1) * K + k0 + ac];
            rb0 = bok ? *(const float4*)&B[(size_t)(k0 + bk0) * N + gn] : make_float4(0,0,0,0);
            rb1 = bok ? *(const float4*)&B[(size_t)(k0 + bk1) * N + gn] : make_float4(0,0,0,0);
        }

#pragma unroll
        for (int ks = 0; ks < 16; ks += 8) {
            float a[4][4], b[4][2];
#pragma unroll
            for (int i = 0; i < 4; i++) {
                const float* p0 = &As[buf][wr + i * 16 + qid][ks + rid];
                const float* p1 = &As[buf][wr + i * 16 + qid + 8][ks + rid];
                a[i][0] = p0[0];
                a[i][1] = p1[0];
                a[i][2] = p0[4];
                a[i][3] = p1[4];
            }
#pragma unroll
            for (int j = 0; j < 4; j++) {
                b[j][0] = Bs[buf][ks + rid][wc + j * 8 + qid];
                b[j][1] = Bs[buf][ks + rid + 4][wc + j * 8 + qid];
            }
#pragma unroll
            for (int i = 0; i < 4; i++)
#pragma unroll
                for (int j = 0; j < 4; j++)
                    mma_tf32(acc[i][j][0], acc[i][j][1], acc[i][j][2], acc[i][j][3],
                             a[i][0], a[i][1], a[i][2], a[i][3],
                             b[j][0], b[j][1]);
        }

        if (t + 1 < nt) {
            const int nb = (t + 1) & 1;
            *(float4*)&As[nb][ar0][ac] = to_tf32x4(ra0);
            *(float4*)&As[nb][ar1][ac] = to_tf32x4(ra1);
            *(float4*)&Bs[nb][bk0][bn] = to_tf32x4(rb0);
            *(float4*)&Bs[nb][bk1][bn] = to_tf32x4(rb1);
        }
        __syncthreads();
    }

#pragma unroll
    for (int i = 0; i < 4; i++) {
        const int r0 = rowBase + wr + i * 16 + qid;
#pragma unroll
        for (int j = 0; j < 4; j++) {
            const int col = colBase + wc + j * 8 + rid * 2;
            if (col < N) {
                *(float2*)&C[(size_t)r0 * N + col]       = make_float2(acc[i][j][0], acc[i][j][1]);
                *(float2*)&C[(size_t)(r0 + 8) * N + col] = make_float2(acc[i][j][2], acc[i][j][3]);
            }
        }
    }
}

// ---------------------------------------------------------------------------
// RMSNorm (in place)
// ---------------------------------------------------------------------------
__global__ void rmsnorm_kernel(float* __restrict__ x,
                               const float* __restrict__ scale, int D)
{
    __shared__ float red[32];
    float* p = x + (size_t)blockIdx.x * D;

    float ss = 0.f;
    for (int d = threadIdx.x; d < D; d += blockDim.x) {
        float v = p[d];
        ss += v * v;
    }
#pragma unroll
    for (int o = 16; o; o >>= 1) ss += __shfl_xor_sync(0xffffffffu, ss, o);
    if ((threadIdx.x & 31) == 0) red[threadIdx.x >> 5] = ss;
    __syncthreads();
    if (threadIdx.x < 32) {
        float v = (threadIdx.x < (blockDim.x >> 5)) ? red[threadIdx.x] : 0.f;
#pragma unroll
        for (int o = 16; o; o >>= 1) v += __shfl_xor_sync(0xffffffffu, v, o);
        if (threadIdx.x == 0) red[0] = v;
    }
    __syncthreads();
    float inv = rsqrtf(red[0] / (float)D + EPS);
    for (int d = threadIdx.x; d < D; d += blockDim.x)
        p[d] = p[d] * inv * scale[d];
}

// ---------------------------------------------------------------------------
// RoPE tables / application
// ---------------------------------------------------------------------------
__global__ void rope_table_kernel(float* __restrict__ ctab, float* __restrict__ stab)
{
    int idx = blockIdx.x * blockDim.x + threadIdx.x;
    if (idx >= S * (ROPE / 2)) return;
    int i = idx % (ROPE / 2);
    int s = idx / (ROPE / 2);
    float freq = (float)pow(10000.0, -((double)(2 * i)) / (double)ROPE);
    float ang  = (float)s * freq;
    double a   = (double)ang;
    ctab[idx] = (float)cos(a);
    stab[idx] = (float)sin(a);
}

__global__ void rope_q_kernel(float* __restrict__ q,
                              const float* __restrict__ ctab,
                              const float* __restrict__ stab)
{
    int idx = blockIdx.x * blockDim.x + threadIdx.x;
    if (idx >= T * NH * (ROPE / 2)) return;
    int i   = idx & 31;
    int rem = idx >> 5;
    int h   = rem & (NH - 1);
    int tok = rem >> 4;
    int s   = tok & (S - 1);
    float c  = ctab[s * 32 + i];
    float sn = stab[s * 32 + i];
    float* p = q + (size_t)tok * (NH * ROPE) + h * ROPE + 2 * i;
    float x1 = p[0], x2 = p[1];
    p[0] = x1 * c - x2 * sn;
    p[1] = x1 * sn + x2 * c;
}

__global__ void rope_k_kernel(float* __restrict__ k,
                              const float* __restrict__ ctab,
                              const float* __restrict__ stab)
{
    int idx = blockIdx.x * blockDim.x + threadIdx.x;
    if (idx >= T * (ROPE / 2)) return;
    int i   = idx & 31;
    int tok = idx >> 5;
    int s   = tok & (S - 1);
    float c  = ctab[s * 32 + i];
    float sn = stab[s * 32 + i];
    float* p = k + (size_t)tok * ROPE + 2 * i;
    float x1 = p[0], x2 = p[1];
    p[0] = (x1 * c - x2 * sn) * 0.0625f;   // /NH folded in
    p[1] = (x1 * sn + x2 * c) * 0.0625f;
}

// ---------------------------------------------------------------------------
// Flash attention: BQ=128 query tile, 512 threads (16 warps), single CTA/SM.
// QK^T and PV both on tf32 mma; conflict-free smem patterns as before.
// ---------------------------------------------------------------------------
constexpr int BQ  = 128;
constexpr int BKT = 64;
constexpr int VSTR = 136;  // V row stride: rid*8+qid covers all 32 banks
constexpr int PSTR = 68;   // P row stride: qid*4+rid covers all 32 banks

struct AttnSmem {
    float Qf[8 * 24 * 32 * 4];   // QK A-frag layout (8 mtiles x 24 ksteps)
    float Kf[8 * 24 * 32 * 2];   // QK B-frag layout (8 ntiles x 24 ksteps)
    float V[BKT][VSTR];
    float P[BQ][PSTR];
    float alpha[BQ];
    float invl[BQ];
};

__global__ void __launch_bounds__(512)
attn_kernel(const float* __restrict__ qn, const float* __restrict__ qr,
            const float* __restrict__ kn, const float* __restrict__ kr,
            const float* __restrict__ v,  float* __restrict__ out)
{
    extern __shared__ char smraw[];
    AttnSmem& sm = *reinterpret_cast<AttnSmem*>(smraw);

    const int qt = blockIdx.x;
    const int h  = blockIdx.y;
    const int b  = blockIdx.z;
    const int tid = threadIdx.x;
    const int lane = tid & 31;
    const int warp = tid >> 5;          // 0..15
    const int qid  = lane >> 2;
    const int rid  = lane & 3;
    const int qb = b * S + qt * BQ;

    // QK warp mapping: rows (warp&7)*16, cols (warp>>3)*32
    const int mtile = warp & 7;
    const int ntb   = (warp >> 3) * 4;
    // PV warp mapping: rows (warp&7)*16 (+qid, +8), cols (warp>>3)*64
    const int row0 = mtile * 16 + qid;
    const int nbv  = (warp >> 3) * 64;

    // ---- load Q tile [128 x 192] into fragment layout ----
    for (int idx = tid; idx < BQ * 32; idx += 512) {
        int r = idx >> 5, dq = (idx & 31) * 4;
        float4 vq = *(const float4*)&qn[(size_t)(qb + r) * (NH * NOPE) + h * NOPE + dq];
        st_afrag<24>(sm.Qf, r, dq, vq);
    }
    for (int idx = tid; idx < BQ * 16; idx += 512) {
        int r = idx >> 4, dq = (idx & 15) * 4;
        float4 vq = *(const float4*)&qr[(size_t)(qb + r) * (NH * ROPE) + h * ROPE + dq];
        st_afrag<24>(sm.Qf, r, 128 + dq, vq);
    }

    const int srow = tid >> 2, squad = tid & 3;   // softmax mapping (128 x 4)

    float m = -1e30f, l = 0.f;
    float acc[8][4];                               // PV accumulators (mma C layout)
#pragma unroll
    for (int j = 0; j < 8; j++)
#pragma unroll
        for (int c = 0; c < 4; c++) acc[j][c] = 0.f;

    const int nkt = 2 * qt + 2;                    // causal: keys up to (qt+1)*128
    for (int kt = 0; kt < nkt; kt++) {
        const int kbT = b * S + kt * BKT;
        __syncthreads();

        // ---- load K tile (frag layout) + V tile (raw, tf32-rounded) ----
        for (int idx = tid; idx < BKT * 32; idx += 512) {
            int r = idx >> 5, dq = (idx & 31) * 4;
            float4 vk = *(const float4*)&kn[(size_t)(kbT + r) * (NH * NOPE) + h * NOPE + dq];
            st_bfrag_kvar<24>(sm.Kf, r, dq, vk);
        }
        for (int idx = tid; idx < BKT * 16; idx += 512) {
            int r = idx >> 4, dq = (idx & 15) * 4;
            float4 vk = *(const float4*)&kr[(size_t)(kbT + r) * ROPE + dq];
            st_bfrag_kvar<24>(sm.Kf, r, 128 + dq, vk);
        }
        for (int idx = tid; idx < BKT * 32; idx += 512) {
            int r = idx >> 5, dq = (idx & 31) * 4;
            float4 vv4 = *(const float4*)&v[(size_t)(kbT + r) * (NH * VD) + h * VD + dq];
            *(float4*)&sm.V[r][dq] = to_tf32x4(vv4);
        }
        __syncthreads();

        // ---- scores via tf32 mma: each warp 16x32 of the 128x64 tile ----
        {
            float c[4][4];
#pragma unroll
            for (int j = 0; j < 4; j++)
#pragma unroll
                for (int cc = 0; cc < 4; cc++) c[j][cc] = 0.f;

#pragma unroll
            for (int ks = 0; ks < 24; ks++) {
                float4 a = *(const float4*)&sm.Qf[((mtile * 24 + ks) * 32 + lane) * 4];
#pragma unroll
                for (int j = 0; j < 4; j++) {
                    float2 bb = *(const float2*)&sm.Kf[(((ntb + j) * 24 + ks) * 32 + lane) * 2];
                    mma_tf32(c[j][0], c[j][1], c[j][2], c[j][3],
                             a.x, a.y, a.z, a.w, bb.x, bb.y);
                }
            }

            const bool diag = (kt >= 2 * qt);      // only last two k-tiles can mask
            const int r0 = mtile * 16 + qid;
#pragma unroll
            for (int j = 0; j < 4; j++) {
                int col = (ntb + j) * 8 + rid * 2;
                int ki0 = kt * BKT + col;
                float s0 = c[j][0] * SM_SCALE, s1 = c[j][1] * SM_SCALE;
                float s2 = c[j][2] * SM_SCALE, s3 = c[j][3] * SM_SCALE;
                if (diag) {
                    int qi0 = qt * BQ + r0;
                    int qi1 = qi0 + 8;
                    if (ki0     > qi0) s0 = -1e9f;
                    if (ki0 + 1 > qi0) s1 = -1e9f;
                    if (ki0     > qi1) s2 = -1e9f;
                    if (ki0 + 1 > qi1) s3 = -1e9f;
                }
                *(float2*)&sm.P[r0][col]     = make_float2(s0, s1);
                *(float2*)&sm.P[r0 + 8][col] = make_float2(s2, s3);
            }
        }
        __syncthreads();

        // ---- online softmax (l in fp32; P stored tf32 for the PV mma) ----
        {
            float sv[16];
            float tmax = -1e30f;
#pragma unroll
            for (int jj = 0; jj < 16; jj++) {
                sv[jj] = sm.P[srow][squad * 16 + jj];
                tmax = fmaxf(tmax, sv[jj]);
            }
            tmax = fmaxf(tmax, __shfl_xor_sync(0xffffffffu, tmax, 1));
            tmax = fmaxf(tmax, __shfl_xor_sync(0xffffffffu, tmax, 2));
            float mnew = fmaxf(m, tmax);
            float al   = __expf(m - mnew);
            float ps = 0.f;
#pragma unroll
            for (int jj = 0; jj < 16; jj++) {
                float p = __expf(sv[jj] - mnew);
                sm.P[srow][squad * 16 + jj] = to_tf32(p);
                ps += p;
            }
            ps += __shfl_xor_sync(0xffffffffu, ps, 1);
            ps += __shfl_xor_sync(0xffffffffu, ps, 2);
            l = l * al + ps;
            m = mnew;
            if (squad == 0) sm.alpha[srow] = al;
        }
        __syncthreads();

        // ---- O = O*alpha + P @ V via tf32 mma ----
        {
            const float al0 = sm.alpha[row0];
            const float al1 = sm.alpha[row0 + 8];
#pragma unroll
            for (int j = 0; j < 8; j++) {
                acc[j][0] *= al0; acc[j][1] *= al0;
                acc[j][2] *= al1; acc[j][3] *= al1;
            }
#pragma unroll
            for (int ks = 0; ks < 8; ks++) {
                const float a0 = sm.P[row0]    [ks * 8 + rid];
                const float a1 = sm.P[row0 + 8][ks * 8 + rid];
                const float a2 = sm.P[row0]    [ks * 8 + rid + 4];
                const float a3 = sm.P[row0 + 8][ks * 8 + rid + 4];
#pragma unroll
                for (int j = 0; j < 8; j++) {
                    const float b0 = sm.V[ks * 8 + rid]    [nbv + j * 8 + qid];
                    const float b1 = sm.V[ks * 8 + rid + 4][nbv + j * 8 + qid];
                    mma_tf32(acc[j][0], acc[j][1], acc[j][2], acc[j][3],
                             a0, a1, a2, a3, b0, b1);
                }
            }
        }
    }

    if (squad == 0) sm.invl[srow] = 1.f / l;
    __syncthreads();

    // ---- epilogue: scale by 1/l, write out (mma C layout) ----
    {
        const float il0 = sm.invl[row0];
        const float il1 = sm.invl[row0 + 8];
        const int tok0 = qb + row0;
        const int tok1 = tok0 + 8;
#pragma unroll
        for (int j = 0; j < 8; j++) {
            const int col = nbv + j * 8 + rid * 2;
            *(float2*)&out[(size_t)tok0 * (NH * VD) + h * VD + col] =
                make_float2(acc[j][0] * il0, acc[j][1] * il0);
            *(float2*)&out[(size_t)tok1 * (NH * VD) + h * VD + col] =
                make_float2(acc[j][2] * il1, acc[j][3] * il1);
        }
    }
}

// ---------------------------------------------------------------------------
// Launch
// ---------------------------------------------------------------------------
static void launch_gemm(const float* A, const float* B, float* C,
                        int M, int N, int K)
{
    dim3 grid((N + 127) / 128, (M + 127) / 128);
    tf32_gemm_kernel<<<grid, 256>>>(A, B, C, M, N, K);
}

extern "C" void kernel_launch(void* const* d_in, const int* in_sizes, int n_in,
                              void* d_out, int out_size)
{
    const float* x         = (const float*)d_in[0];
    const float* W_cq      = (const float*)d_in[1];
    const float* q_scale   = (const float*)d_in[2];
    const float* W_dq_nope = (const float*)d_in[3];
    const float* W_dq_rope = (const float*)d_in[4];
    const float* W_ckv     = (const float*)d_in[5];
    const float* kv_scale  = (const float*)d_in[6];
    const float* W_dk_nope = (const float*)d_in[7];
    const float* W_dv      = (const float*)d_in[8];
    const float* W_krope   = (const float*)d_in[9];
    const float* W_o       = (const float*)d_in[10];
    float* out = (float*)d_out;

    float *cq, *qn, *qr, *ckv, *kn, *vv, *kr, *att, *ctab, *stab;
    cudaGetSymbolAddress((void**)&cq,  g_cq);
    cudaGetSymbolAddress((void**)&qn,  g_qnope);
    cudaGetSymbolAddress((void**)&qr,  g_qrope);
    cudaGetSymbolAddress((void**)&ckv, g_ckv);
    cudaGetSymbolAddress((void**)&kn,  g_knope);
    cudaGetSymbolAddress((void**)&vv,  g_v);
    cudaGetSymbolAddress((void**)&kr,  g_krope);
    cudaGetSymbolAddress((void**)&att, g_attn);
    cudaGetSymbolAddress((void**)&ctab, g_ctab);
    cudaGetSymbolAddress((void**)&stab, g_stab);

    // RoPE tables
    rope_table_kernel<<<(S * 32 + 255) / 256, 256>>>(ctab, stab);

    // Q path
    launch_gemm(x, W_cq, cq, T, QR, H);
    rmsnorm_kernel<<<T, 256>>>(cq, q_scale, QR);
    launch_gemm(cq, W_dq_nope, qn, T, NH * NOPE, QR);
    launch_gemm(cq, W_dq_rope, qr, T, NH * ROPE, QR);
    rope_q_kernel<<<(T * NH * 32 + 255) / 256, 256>>>(qr, ctab, stab);

    // KV path
    launch_gemm(x, W_ckv, ckv, T, KVR, H);
    rmsnorm_kernel<<<T, 256>>>(ckv, kv_scale, KVR);
    launch_gemm(ckv, W_dk_nope, kn, T, NH * NOPE, KVR);
    launch_gemm(ckv, W_dv, vv, T, NH * VD, KVR);
    launch_gemm(x, W_krope, kr, T, ROPE, H);
    rope_k_kernel<<<(T * 32 + 255) / 256, 256>>>(kr, ctab, stab);

    // Attention
    cudaFuncSetAttribute((const void*)attn_kernel,
                         cudaFuncAttributeMaxDynamicSharedMemorySize,
                         (int)sizeof(AttnSmem));
    attn_kernel<<<dim3(S / BQ, NH, BB), 512, sizeof(AttnSmem)>>>(qn, qr, kn, kr, vv, att);

    // Output projection
    launch_gemm(att, W_o, out, T, H, NH * VD);
}

// round 8
// speedup vs baseline: 1.0578x; 1.0578x over previous
#include <cuda_runtime.h>
#include <math.h>
#include <stdint.h>

// ---------------------------------------------------------------------------
// Problem constants
// ---------------------------------------------------------------------------
constexpr int H    = 2048;
constexpr int NH   = 16;
constexpr int NOPE = 128;
constexpr int ROPE = 64;
constexpr int VD   = 128;
constexpr int QR   = 1024;
constexpr int KVR  = 512;
constexpr int BB   = 2;       // batch
constexpr int S    = 2048;    // seq len
constexpr int T    = BB * S;  // 4096 tokens
constexpr float EPS = 1e-6f;
constexpr float SM_SCALE = 0.07216878364870323f; // 1/sqrt(192)

// ---------------------------------------------------------------------------
// Device scratch (allocation-free rule: __device__ globals)
// ---------------------------------------------------------------------------
__device__ float g_cq   [T * QR];
__device__ float g_qnope[T * NH * NOPE];
__device__ float g_qrope[T * NH * ROPE];
__device__ float g_ckv  [T * KVR];
__device__ float g_knope[T * NH * NOPE];
__device__ float g_v    [T * NH * VD];
__device__ float g_krope[T * ROPE];
__device__ float g_attn [T * NH * VD];
__device__ float g_ctab [S * (ROPE / 2)];
__device__ float g_stab [S * (ROPE / 2)];

// ---------------------------------------------------------------------------
// tf32 helpers
// ---------------------------------------------------------------------------
__device__ __forceinline__ float to_tf32(float x) {
    uint32_t u;
    asm("cvt.rna.tf32.f32 %0, %1;" : "=r"(u) : "f"(x));
    return __uint_as_float(u);
}
__device__ __forceinline__ float4 to_tf32x4(float4 v) {
    return make_float4(to_tf32(v.x), to_tf32(v.y), to_tf32(v.z), to_tf32(v.w));
}

__device__ __forceinline__ void mma_tf32(float& c0, float& c1, float& c2, float& c3,
                                         float a0, float a1, float a2, float a3,
                                         float b0, float b1)
{
    uint32_t ua0 = __float_as_uint(a0), ua1 = __float_as_uint(a1);
    uint32_t ua2 = __float_as_uint(a2), ua3 = __float_as_uint(a3);
    uint32_t ub0 = __float_as_uint(b0), ub1 = __float_as_uint(b1);
    asm volatile(
        "mma.sync.aligned.m16n8k8.row.col.f32.tf32.tf32.f32 "
        "{%0,%1,%2,%3}, {%4,%5,%6,%7}, {%8,%9}, {%0,%1,%2,%3};\n"
        : "+f"(c0), "+f"(c1), "+f"(c2), "+f"(c3)
        : "r"(ua0), "r"(ua1), "r"(ua2), "r"(ua3), "r"(ub0), "r"(ub1));
}

// Fragment-order smem stores (values already tf32-rounded by producers).
template<int KSTEPS>
__device__ __forceinline__ void st_afrag_raw(float* F, int m, int k, float4 v) {
    float* dst = F + (((m >> 4) * KSTEPS + (k >> 3)) * 32 + (m & 7) * 4 + (k & 3)) * 4
                   + ((m >> 3) & 1) + (((k >> 2) & 1) << 1);
    dst[0]  = v.x;
    dst[4]  = v.y;
    dst[8]  = v.z;
    dst[12] = v.w;
}
template<int KSTEPS>
__device__ __forceinline__ void st_bfrag_raw(float* F, int r, int d, float4 v) {
    float* dst = F + (((r >> 3) * KSTEPS + (d >> 3)) * 32 + (r & 7) * 4 + (d & 3)) * 2
                   + ((d >> 2) & 1);
    dst[0] = v.x;
    dst[2] = v.y;
    dst[4] = v.z;
    dst[6] = v.w;
}

// ---------------------------------------------------------------------------
// tf32 tensor-core GEMM (proven): C[M,N] = A[M,K] @ B[K,N].
// round_out != 0 -> store tf32-rounded results (for attention inputs).
// ---------------------------------------------------------------------------
constexpr int AS_STRIDE = 20;
constexpr int BS_STRIDE = 136;

__global__ void __launch_bounds__(256)
tf32_gemm_kernel(const float* __restrict__ A, const float* __restrict__ B,
                 float* __restrict__ C, int M, int N, int K, int round_out)
{
    __shared__ float As[2][128][AS_STRIDE];
    __shared__ float Bs[2][16][BS_STRIDE];

    const int tid  = threadIdx.x;
    const int lane = tid & 31;
    const int warp = tid >> 5;
    const int qid  = lane >> 2;
    const int rid  = lane & 3;
    const int wr   = (warp >> 2) * 64;
    const int wc   = (warp & 3) * 32;

    const int rowBase = blockIdx.y * 128;
    const int colBase = blockIdx.x * 128;

    const int ar0 = tid >> 2;
    const int ar1 = ar0 + 64;
    const int ac  = (tid & 3) * 4;
    const int bk0 = tid >> 5;
    const int bk1 = bk0 + 8;
    const int bn  = (tid & 31) * 4;
    const int gn  = colBase + bn;
    const bool bok = (gn < N);

    float acc[4][4][4];
#pragma unroll
    for (int i = 0; i < 4; i++)
#pragma unroll
        for (int j = 0; j < 4; j++)
#pragma unroll
            for (int c = 0; c < 4; c++) acc[i][j][c] = 0.f;

    const int nt = K / 16;
    float4 ra0, ra1, rb0, rb1;

    ra0 = *(const float4*)&A[(size_t)(rowBase + ar0) * K + ac];
    ra1 = *(const float4*)&A[(size_t)(rowBase + ar1) * K + ac];
    rb0 = bok ? *(const float4*)&B[(size_t)bk0 * N + gn] : make_float4(0,0,0,0);
    rb1 = bok ? *(const float4*)&B[(size_t)bk1 * N + gn] : make_float4(0,0,0,0);
    *(float4*)&As[0][ar0][ac] = to_tf32x4(ra0);
    *(float4*)&As[0][ar1][ac] = to_tf32x4(ra1);
    *(float4*)&Bs[0][bk0][bn] = to_tf32x4(rb0);
    *(float4*)&Bs[0][bk1][bn] = to_tf32x4(rb1);
    __syncthreads();

    for (int t = 0; t < nt; t++) {
        const int buf = t & 1;

        if (t + 1 < nt) {
            const int k0 = (t + 1) * 16;
            ra0 = *(const float4*)&A[(size_t)(rowBase + ar0) * K + k0 + ac];
            ra1 = *(const float4*)&A[(size_t)(rowBase + ar1) * K + k0 + ac];
            rb0 = bok ? *(const float4*)&B[(size_t)(k0 + bk0) * N + gn] : make_float4(0,0,0,0);
            rb1 = bok ? *(const float4*)&B[(size_t)(k0 + bk1) * N + gn] : make_float4(0,0,0,0);
        }

#pragma unroll
        for (int ks = 0; ks < 16; ks += 8) {
            float a[4][4], b[4][2];
#pragma unroll
            for (int i = 0; i < 4; i++) {
                const float* p0 = &As[buf][wr + i * 16 + qid][ks + rid];
                const float* p1 = &As[buf][wr + i * 16 + qid + 8][ks + rid];
                a[i][0] = p0[0];
                a[i][1] = p1[0];
                a[i][2] = p0[4];
                a[i][3] = p1[4];
            }
#pragma unroll
            for (int j = 0; j < 4; j++) {
                b[j][0] = Bs[buf][ks + rid][wc + j * 8 + qid];
                b[j][1] = Bs[buf][ks + rid + 4][wc + j * 8 + qid];
            }
#pragma unroll
            for (int i = 0; i < 4; i++)
#pragma unroll
                for (int j = 0; j < 4; j++)
                    mma_tf32(acc[i][j][0], acc[i][j][1], acc[i][j][2], acc[i][j][3],
                             a[i][0], a[i][1], a[i][2], a[i][3],
                             b[j][0], b[j][1]);
        }

        if (t + 1 < nt) {
            const int nb = (t + 1) & 1;
            *(float4*)&As[nb][ar0][ac] = to_tf32x4(ra0);
            *(float4*)&As[nb][ar1][ac] = to_tf32x4(ra1);
            *(float4*)&Bs[nb][bk0][bn] = to_tf32x4(rb0);
            *(float4*)&Bs[nb][bk1][bn] = to_tf32x4(rb1);
        }
        __syncthreads();
    }

#pragma unroll
    for (int i = 0; i < 4; i++) {
        const int r0 = rowBase + wr + i * 16 + qid;
#pragma unroll
        for (int j = 0; j < 4; j++) {
            const int col = colBase + wc + j * 8 + rid * 2;
            if (col < N) {
                float2 v0 = make_float2(acc[i][j][0], acc[i][j][1]);
                float2 v1 = make_float2(acc[i][j][2], acc[i][j][3]);
                if (round_out) {
                    v0.x = to_tf32(v0.x); v0.y = to_tf32(v0.y);
                    v1.x = to_tf32(v1.x); v1.y = to_tf32(v1.y);
                }
                *(float2*)&C[(size_t)r0 * N + col]       = v0;
                *(float2*)&C[(size_t)(r0 + 8) * N + col] = v1;
            }
        }
    }
}

// ---------------------------------------------------------------------------
// RMSNorm (in place)
// ---------------------------------------------------------------------------
__global__ void rmsnorm_kernel(float* __restrict__ x,
                               const float* __restrict__ scale, int D)
{
    __shared__ float red[32];
    float* p = x + (size_t)blockIdx.x * D;

    float ss = 0.f;
    for (int d = threadIdx.x; d < D; d += blockDim.x) {
        float v = p[d];
        ss += v * v;
    }
#pragma unroll
    for (int o = 16; o; o >>= 1) ss += __shfl_xor_sync(0xffffffffu, ss, o);
    if ((threadIdx.x & 31) == 0) red[threadIdx.x >> 5] = ss;
    __syncthreads();
    if (threadIdx.x < 32) {
        float v = (threadIdx.x < (blockDim.x >> 5)) ? red[threadIdx.x] : 0.f;
#pragma unroll
        for (int o = 16; o; o >>= 1) v += __shfl_xor_sync(0xffffffffu, v, o);
        if (threadIdx.x == 0) red[0] = v;
    }
    __syncthreads();
    float inv = rsqrtf(red[0] / (float)D + EPS);
    for (int d = threadIdx.x; d < D; d += blockDim.x)
        p[d] = p[d] * inv * scale[d];
}

// ---------------------------------------------------------------------------
// RoPE tables / application (rope outputs tf32-rounded: consumed only by mma)
// ---------------------------------------------------------------------------
__global__ void rope_table_kernel(float* __restrict__ ctab, float* __restrict__ stab)
{
    int idx = blockIdx.x * blockDim.x + threadIdx.x;
    if (idx >= S * (ROPE / 2)) return;
    int i = idx % (ROPE / 2);
    int s = idx / (ROPE / 2);
    float freq = (float)pow(10000.0, -((double)(2 * i)) / (double)ROPE);
    float ang  = (float)s * freq;
    double a   = (double)ang;
    ctab[idx] = (float)cos(a);
    stab[idx] = (float)sin(a);
}

__global__ void rope_q_kernel(float* __restrict__ q,
                              const float* __restrict__ ctab,
                              const float* __restrict__ stab)
{
    int idx = blockIdx.x * blockDim.x + threadIdx.x;
    if (idx >= T * NH * (ROPE / 2)) return;
    int i   = idx & 31;
    int rem = idx >> 5;
    int h   = rem & (NH - 1);
    int tok = rem >> 4;
    int s   = tok & (S - 1);
    float c  = ctab[s * 32 + i];
    float sn = stab[s * 32 + i];
    float* p = q + (size_t)tok * (NH * ROPE) + h * ROPE + 2 * i;
    float x1 = p[0], x2 = p[1];
    p[0] = to_tf32(x1 * c - x2 * sn);
    p[1] = to_tf32(x1 * sn + x2 * c);
}

__global__ void rope_k_kernel(float* __restrict__ k,
                              const float* __restrict__ ctab,
                              const float* __restrict__ stab)
{
    int idx = blockIdx.x * blockDim.x + threadIdx.x;
    if (idx >= T * (ROPE / 2)) return;
    int i   = idx & 31;
    int tok = idx >> 5;
    int s   = tok & (S - 1);
    float c  = ctab[s * 32 + i];
    float sn = stab[s * 32 + i];
    float* p = k + (size_t)tok * ROPE + 2 * i;
    float x1 = p[0], x2 = p[1];
    p[0] = to_tf32((x1 * c - x2 * sn) * 0.0625f);   // /NH folded in
    p[1] = to_tf32((x1 * sn + x2 * c) * 0.0625f);
}

// ---------------------------------------------------------------------------
// Flash attention: BQ=128, 512 threads. Register-prefetch pipeline for K/V
// (LDG for tile t+1 issued before tile t's compute; STS at next iteration).
// All inputs pre-rounded to tf32 by producers -> staging is a pure permute.
// ---------------------------------------------------------------------------
constexpr int BQ  = 128;
constexpr int BKT = 64;
constexpr int VSTR = 136;
constexpr int PSTR = 68;

struct AttnSmem {
    float Qf[8 * 24 * 32 * 4];
    float Kf[8 * 24 * 32 * 2];
    float V[BKT][VSTR];
    float P[BQ][PSTR];
    float alpha[BQ];
    float invl[BQ];
};

__global__ void __launch_bounds__(512)
attn_kernel(const float* __restrict__ qn, const float* __restrict__ qr,
            const float* __restrict__ kn, const float* __restrict__ kr,
            const float* __restrict__ v,  float* __restrict__ out)
{
    extern __shared__ char smraw[];
    AttnSmem& sm = *reinterpret_cast<AttnSmem*>(smraw);

    const int qt = (gridDim.x - 1) - blockIdx.x;   // heavy blocks first
    const int h  = blockIdx.y;
    const int b  = blockIdx.z;
    const int tid = threadIdx.x;
    const int lane = tid & 31;
    const int warp = tid >> 5;
    const int qid  = lane >> 2;
    const int rid  = lane & 3;
    const int qb = b * S + qt * BQ;

    const int mtile = warp & 7;
    const int ntb   = (warp >> 3) * 4;
    const int row0 = mtile * 16 + qid;
    const int nbv  = (warp >> 3) * 64;

    // per-thread staging indices (fixed)
    const int krn[4] = { tid >> 5, (tid + 512) >> 5, (tid + 1024) >> 5, (tid + 1536) >> 5 };
    const int kcn    = (tid & 31) * 4;
    const int krr[2] = { tid >> 4, (tid + 512) >> 4 };
    const int kcr    = (tid & 15) * 4;

    // ---- stage Q tile [128 x 192] into fragment layout ----
    for (int idx = tid; idx < BQ * 32; idx += 512) {
        int r = idx >> 5, dq = (idx & 31) * 4;
        st_afrag_raw<24>(sm.Qf, r, dq,
            *(const float4*)&qn[(size_t)(qb + r) * (NH * NOPE) + h * NOPE + dq]);
    }
    for (int idx = tid; idx < BQ * 16; idx += 512) {
        int r = idx >> 4, dq = (idx & 15) * 4;
        st_afrag_raw<24>(sm.Qf, r, 128 + dq,
            *(const float4*)&qr[(size_t)(qb + r) * (NH * ROPE) + h * ROPE + dq]);
    }

    const int srow = tid >> 2, squad = tid & 3;

    float m = -1e30f, l = 0.f;
    float acc[8][4];
#pragma unroll
    for (int j = 0; j < 8; j++)
#pragma unroll
        for (int c = 0; c < 4; c++) acc[j][c] = 0.f;

    const int nkt = 2 * qt + 2;

    // ---- prefetch tile 0 into registers ----
    float4 kb[6], vb[4];
    {
        const int kbT = b * S;
#pragma unroll
        for (int i = 0; i < 4; i++)
            kb[i] = *(const float4*)&kn[(size_t)(kbT + krn[i]) * (NH * NOPE) + h * NOPE + kcn];
#pragma unroll
        for (int i = 0; i < 2; i++)
            kb[4 + i] = *(const float4*)&kr[(size_t)(kbT + krr[i]) * ROPE + kcr];
#pragma unroll
        for (int i = 0; i < 4; i++)
            vb[i] = *(const float4*)&v[(size_t)(kbT + krn[i]) * (NH * VD) + h * VD + kcn];
    }

    for (int kt = 0; kt < nkt; kt++) {
        __syncthreads();   // Kf/V free (prev QK/PV done) and Q staging visible

        // ---- store prefetched tile to smem ----
#pragma unroll
        for (int i = 0; i < 4; i++) st_bfrag_raw<24>(sm.Kf, krn[i], kcn, kb[i]);
#pragma unroll
        for (int i = 0; i < 2; i++) st_bfrag_raw<24>(sm.Kf, krr[i], 128 + kcr, kb[4 + i]);
#pragma unroll
        for (int i = 0; i < 4; i++) *(float4*)&sm.V[krn[i]][kcn] = vb[i];
        __syncthreads();   // tile kt ready

        // ---- issue prefetch for tile kt+1 (latency hidden under compute) ----
        if (kt + 1 < nkt) {
            const int kbT = b * S + (kt + 1) * BKT;
#pragma unroll
            for (int i = 0; i < 4; i++)
                kb[i] = *(const float4*)&kn[(size_t)(kbT + krn[i]) * (NH * NOPE) + h * NOPE + kcn];
#pragma unroll
            for (int i = 0; i < 2; i++)
                kb[4 + i] = *(const float4*)&kr[(size_t)(kbT + krr[i]) * ROPE + kcr];
#pragma unroll
            for (int i = 0; i < 4; i++)
                vb[i] = *(const float4*)&v[(size_t)(kbT + krn[i]) * (NH * VD) + h * VD + kcn];
        }

        // ---- scores via tf32 mma: each warp 16x32 of the 128x64 tile ----
        {
            float c[4][4];
#pragma unroll
            for (int j = 0; j < 4; j++)
#pragma unroll
                for (int cc = 0; cc < 4; cc++) c[j][cc] = 0.f;

#pragma unroll
            for (int ks = 0; ks < 24; ks++) {
                float4 a = *(const float4*)&sm.Qf[((mtile * 24 + ks) * 32 + lane) * 4];
#pragma unroll
                for (int j = 0; j < 4; j++) {
                    float2 bb = *(const float2*)&sm.Kf[(((ntb + j) * 24 + ks) * 32 + lane) * 2];
                    mma_tf32(c[j][0], c[j][1], c[j][2], c[j][3],
                             a.x, a.y, a.z, a.w, bb.x, bb.y);
                }
            }

            const bool diag = (kt >= 2 * qt);
            const int r0 = mtile * 16 + qid;
#pragma unroll
            for (int j = 0; j < 4; j++) {
                int col = (ntb + j) * 8 + rid * 2;
                int ki0 = kt * BKT + col;
                float s0 = c[j][0] * SM_SCALE, s1 = c[j][1] * SM_SCALE;
                float s2 = c[j][2] * SM_SCALE, s3 = c[j][3] * SM_SCALE;
                if (diag) {
                    int qi0 = qt * BQ + r0;
                    int qi1 = qi0 + 8;
                    if (ki0     > qi0) s0 = -1e9f;
                    if (ki0 + 1 > qi0) s1 = -1e9f;
                    if (ki0     > qi1) s2 = -1e9f;
                    if (ki0 + 1 > qi1) s3 = -1e9f;
                }
                *(float2*)&sm.P[r0][col]     = make_float2(s0, s1);
                *(float2*)&sm.P[r0 + 8][col] = make_float2(s2, s3);
            }
        }
        __syncthreads();

        // ---- online softmax (l in fp32; P stored tf32 for the PV mma) ----
        {
            float sv[16];
            float tmax = -1e30f;
#pragma unroll
            for (int jj = 0; jj < 16; jj++) {
                sv[jj] = sm.P[srow][squad * 16 + jj];
                tmax = fmaxf(tmax, sv[jj]);
            }
            tmax = fmaxf(tmax, __shfl_xor_sync(0xffffffffu, tmax, 1));
            tmax = fmaxf(tmax, __shfl_xor_sync(0xffffffffu, tmax, 2));
            float mnew = fmaxf(m, tmax);
            float al   = __expf(m - mnew);
            float ps = 0.f;
#pragma unroll
            for (int jj = 0; jj < 16; jj++) {
                float p = __expf(sv[jj] - mnew);
                sm.P[srow][squad * 16 + jj] = to_tf32(p);
                ps += p;
            }
            ps += __shfl_xor_sync(0xffffffffu, ps, 1);
            ps += __shfl_xor_sync(0xffffffffu, ps, 2);
            l = l * al + ps;
            m = mnew;
            if (squad == 0) sm.alpha[srow] = al;
        }
        __syncthreads();

        // ---- O = O*alpha + P @ V via tf32 mma ----
        {
            const float al0 = sm.alpha[row0];
            const float al1 = sm.alpha[row0 + 8];
#pragma unroll
            for (int j = 0; j < 8; j++) {
                acc[j][0] *= al0; acc[j][1] *= al0;
                acc[j][2] *= al1; acc[j][3] *= al1;
            }
#pragma unroll
            for (int ks = 0; ks < 8; ks++) {
                const float a0 = sm.P[row0]    [ks * 8 + rid];
                const float a1 = sm.P[row0 + 8][ks * 8 + rid];
                const float a2 = sm.P[row0]    [ks * 8 + rid + 4];
                const float a3 = sm.P[row0 + 8][ks * 8 + rid + 4];
#pragma unroll
                for (int j = 0; j < 8; j++) {
                    const float b0 = sm.V[ks * 8 + rid]    [nbv + j * 8 + qid];
                    const float b1 = sm.V[ks * 8 + rid + 4][nbv + j * 8 + qid];
                    mma_tf32(acc[j][0], acc[j][1], acc[j][2], acc[j][3],
                             a0, a1, a2, a3, b0, b1);
                }
            }
        }
    }

    if (squad == 0) sm.invl[srow] = 1.f / l;
    __syncthreads();

    // ---- epilogue ----
    {
        const float il0 = sm.invl[row0];
        const float il1 = sm.invl[row0 + 8];
        const int tok0 = qb + row0;
        const int tok1 = tok0 + 8;
#pragma unroll
        for (int j = 0; j < 8; j++) {
            const int col = nbv + j * 8 + rid * 2;
            *(float2*)&out[(size_t)tok0 * (NH * VD) + h * VD + col] =
                make_float2(acc[j][0] * il0, acc[j][1] * il0);
            *(float2*)&out[(size_t)tok1 * (NH * VD) + h * VD + col] =
                make_float2(acc[j][2] * il1, acc[j][3] * il1);
        }
    }
}

// ---------------------------------------------------------------------------
// Launch
// ---------------------------------------------------------------------------
static void launch_gemm(const float* A, const float* B, float* C,
                        int M, int N, int K, int round_out = 0)
{
    dim3 grid((N + 127) / 128, (M + 127) / 128);
    tf32_gemm_kernel<<<grid, 256>>>(A, B, C, M, N, K, round_out);
}

extern "C" void kernel_launch(void* const* d_in, const int* in_sizes, int n_in,
                              void* d_out, int out_size)
{
    const float* x         = (const float*)d_in[0];
    const float* W_cq      = (const float*)d_in[1];
    const float* q_scale   = (const float*)d_in[2];
    const float* W_dq_nope = (const float*)d_in[3];
    const float* W_dq_rope = (const float*)d_in[4];
    const float* W_ckv     = (const float*)d_in[5];
    const float* kv_scale  = (const float*)d_in[6];
    const float* W_dk_nope = (const float*)d_in[7];
    const float* W_dv      = (const float*)d_in[8];
    const float* W_krope   = (const float*)d_in[9];
    const float* W_o       = (const float*)d_in[10];
    float* out = (float*)d_out;

    float *cq, *qn, *qr, *ckv, *kn, *vv, *kr, *att, *ctab, *stab;
    cudaGetSymbolAddress((void**)&cq,  g_cq);
    cudaGetSymbolAddress((void**)&qn,  g_qnope);
    cudaGetSymbolAddress((void**)&qr,  g_qrope);
    cudaGetSymbolAddress((void**)&ckv, g_ckv);
    cudaGetSymbolAddress((void**)&kn,  g_knope);
    cudaGetSymbolAddress((void**)&vv,  g_v);
    cudaGetSymbolAddress((void**)&kr,  g_krope);
    cudaGetSymbolAddress((void**)&att, g_attn);
    cudaGetSymbolAddress((void**)&ctab, g_ctab);
    cudaGetSymbolAddress((void**)&stab, g_stab);

    // RoPE tables
    rope_table_kernel<<<(S * 32 + 255) / 256, 256>>>(ctab, stab);

    // Q path
    launch_gemm(x, W_cq, cq, T, QR, H);
    rmsnorm_kernel<<<T, 256>>>(cq, q_scale, QR);
    launch_gemm(cq, W_dq_nope, qn, T, NH * NOPE, QR, 1);   // tf32-rounded out
    launch_gemm(cq, W_dq_rope, qr, T, NH * ROPE, QR);
    rope_q_kernel<<<(T * NH * 32 + 255) / 256, 256>>>(qr, ctab, stab);

    // KV path
    launch_gemm(x, W_ckv, ckv, T, KVR, H);
    rmsnorm_kernel<<<T, 256>>>(ckv, kv_scale, KVR);
    launch_gemm(ckv, W_dk_nope, kn, T, NH * NOPE, KVR, 1); // tf32-rounded out
    launch_gemm(ckv, W_dv, vv, T, NH * VD, KVR, 1);        // tf32-rounded out
    launch_gemm(x, W_krope, kr, T, ROPE, H);
    rope_k_kernel<<<(T * 32 + 255) / 256, 256>>>(kr, ctab, stab);

    // Attention
    cudaFuncSetAttribute((const void*)attn_kernel,
                         cudaFuncAttributeMaxDynamicSharedMemorySize,
                         (int)sizeof(AttnSmem));
    attn_kernel<<<dim3(S / BQ, NH, BB), 512, sizeof(AttnSmem)>>>(qn, qr, kn, kr, vv, att);

    // Output projection
    launch_gemm(att, W_o, out, T, H, NH * VD);
}